// round 15
// baseline (speedup 1.0000x reference)
// R15: double-buffer reverted (R14 post-mortem: staging overhead > barrier
// savings). Adds role rebuilt: NO smem tile, NO barriers — records streamed
// directly via __ldg (L1-resident, ~115KB/batch), Q=8 queries/warp so each
// 64B record feeds 176 FMA. 64 q/block, grid 132, launch_bounds(256,1).
// Arithmetic identical to R12. k_nn1/sel/finalize unchanged.
#include <cuda_runtime.h>
#include <math.h>

#define BB 4
#define NN 2048
#define MM 4096
#define NSPLIT 4
#define MSPL (MM/NSPLIT)         // 1024 contacts per split
#define FARV 100000.0f
#define ADDS_BLOCKS 128          // 64 compacted queries per block (32 blocks/batch)
#define MAIN_BLOCKS (ADDS_BLOCKS + BB)
#define NQGROUP (BB*NN/32)       // 256 query groups of 32

typedef unsigned long long u64;

// ---------------- scratch (device globals; zero-init + self-cleaning) ----------------
__device__ u64      g_nnPart[BB*NN*NSPLIT]; // packed (d_bits<<32)|j partial argmins
__device__ float    g_pos[BB*NN];
__device__ float    g_pri[BB*NN];
__device__ float    g_wlab[BB*NN];
__device__ float4   g_crec[BB*NN*4];        // compacted positive records
__device__ int      g_cidx[BB*NN];          // compacted slot -> global query index
__device__ unsigned g_cnt[BB];              // positives per batch (reset by k_main finalize)
__device__ unsigned g_qtick[NQGROUP];       // per-qgroup tickets (reset by combiner)
__device__ double   g_acc[BB*8];            // 0 posSum,1 bceSum,2 selSum,3 wlSum, 4 addsSum(atomic)
__device__ unsigned g_ticket;               // k_main ticket (reset by finalize)

__constant__ float c_lo[10] = {0.0f, 0.00794435329f, 0.0158887021f, 0.0238330509f, 0.0317773996f,
                               0.0397217484f, 0.0476660972f, 0.0556104459f, 0.0635547947f, 0.0714991435f};
__constant__ float c_hi[10] = {0.00794435329f, 0.0158887021f, 0.0238330509f, 0.0317773996f, 0.0397217484f,
                               0.0476660972f, 0.0556104459f, 0.0635547947f, 0.0714991435f, 0.08f};
__constant__ float c_wt[10] = {0.16652107f, 0.21488856f, 0.37031708f, 0.55618503f, 0.75124664f,
                               0.93943357f, 1.07824539f, 1.19423112f, 1.55731375f, 2.34173634f};

// ---------------- threefry2x32 (JAX-exact, key(42), counts = iota(8192)) ----------------
__device__ __forceinline__ unsigned rotl32(unsigned x, unsigned d){ return (x<<d)|(x>>(32u-d)); }

__device__ __forceinline__ float threefry_uniform_8192(unsigned flat){
  unsigned c0, c1; bool second;
  if (flat < 4096u){ c0 = flat;        c1 = flat + 4096u; second = false; }
  else             { c0 = flat - 4096u; c1 = flat;        second = true;  }
  const unsigned ks0 = 0u, ks1 = 42u, ks2 = 0u ^ 42u ^ 0x1BD11BDAu;
  unsigned x0 = c0 + ks0, x1 = c1 + ks1;
#define TF_ROUND(r) { x0 += x1; x1 = rotl32(x1,(r)); x1 ^= x0; }
  TF_ROUND(13) TF_ROUND(15) TF_ROUND(26) TF_ROUND(6)
  x0 += ks1; x1 += ks2 + 1u;
  TF_ROUND(17) TF_ROUND(29) TF_ROUND(16) TF_ROUND(24)
  x0 += ks2; x1 += ks0 + 2u;
  TF_ROUND(13) TF_ROUND(15) TF_ROUND(26) TF_ROUND(6)
  x0 += ks0; x1 += ks1 + 3u;
  TF_ROUND(17) TF_ROUND(29) TF_ROUND(16) TF_ROUND(24)
  x0 += ks1; x1 += ks2 + 4u;
  TF_ROUND(13) TF_ROUND(15) TF_ROUND(26) TF_ROUND(6)
  x0 += ks2; x1 += ks0 + 5u;
#undef TF_ROUND
  unsigned bits = second ? x1 : x0;
  float f = __uint_as_float((bits >> 9) | 0x3F800000u) - 1.0f;
  return fmaxf(f, 0.0f);
}

// ---------------- K1: partial NN scan + last-block-per-qgroup combine ----------------
__global__ __launch_bounds__(256) void k_nn1(
    const float* __restrict__ pred_points,
    const float* __restrict__ pcp,
    const float* __restrict__ pcw,
    const float* __restrict__ pcr,
    const float* __restrict__ pct,
    const float* __restrict__ cp,
    const float* __restrict__ cps)
{
  __shared__ float4 s_pc[MSPL];     // (x,y,z, 0.5*|c|^2) 16KB
  __shared__ float  s_cp[15], s_cps[15];
  __shared__ bool   s_last;
  int tid = threadIdx.x, lane = tid & 31, warp = tid >> 5;
  int split  = blockIdx.x & (NSPLIT-1);
  int qgroup = blockIdx.x >> 2;
  int q0 = (qgroup*8 + warp)*4;
  int b  = q0 / NN;
  int jb = split*MSPL;

  {
    const float* base = pcp + ((size_t)b*MM + jb)*3;
    for (int j = tid; j < MSPL; j += 256){
      float x = base[j*3+0], y = base[j*3+1], z = base[j*3+2];
      s_pc[j] = make_float4(x, y, z, 0.5f*(x*x + y*y + z*z));
    }
  }
  __syncthreads();

  float nqx[4], nqy[4], nqz[4], qn[4];
#pragma unroll
  for (int k = 0; k < 4; k++){
    const float* p = pred_points + (size_t)(q0+k)*3;
    float px=p[0], py=p[1], pz=p[2];
    nqx[k]=-px; nqy[k]=-py; nqz[k]=-pz;
    qn[k]=px*px+py*py+pz*pz;
  }
  float beste[4] = {3.4e38f,3.4e38f,3.4e38f,3.4e38f};
  int   bidx[4] = {0,0,0,0};
  for (int j = lane; j < MSPL; j += 32){
    float4 c = s_pc[j];
#pragma unroll
    for (int k = 0; k < 4; k++){
      float e = fmaf(nqx[k], c.x, fmaf(nqy[k], c.y, fmaf(nqz[k], c.z, c.w)));
      if (e < beste[k]){ beste[k] = e; bidx[k] = j; }
    }
  }
#pragma unroll
  for (int k = 0; k < 4; k++){
    float d = fmaxf(fmaf(2.0f, beste[k], qn[k]), 0.0f);   // clamped distance
    u64 key = ((u64)__float_as_uint(d) << 32) | (unsigned)(jb + bidx[k]);
#pragma unroll
    for (int off = 16; off; off >>= 1){
      u64 o = __shfl_xor_sync(0xffffffffu, key, off);
      if (o < key) key = o;
    }
    if (lane == k) g_nnPart[(size_t)(q0+k)*NSPLIT + split] = key;
  }

  // ---- qgroup ticket: last of the NSPLIT blocks combines ----
  __threadfence();
  __syncthreads();
  if (tid == 0){
    unsigned tk = atomicAdd(&g_qtick[qgroup], 1u);
    s_last = (tk == NSPLIT - 1u);
  }
  __syncthreads();
  if (!s_last) return;
  __threadfence();   // acquire: see other blocks' partials

  if (tid < 15){ s_cp[tid] = cp[tid]; s_cps[tid] = cps[tid]; }
  if (tid == 0) g_qtick[qgroup] = 0u;   // self-clean for next call
  __syncthreads();

  if (tid < 32){
    int q = qgroup*32 + tid;
    const u64* part = g_nnPart + (size_t)q*NSPLIT;
    u64 key = part[0];
#pragma unroll
    for (int s = 1; s < NSPLIT; s++){ u64 o = part[s]; if (o < key) key = o; }
    float d = __uint_as_float((unsigned)(key >> 32));
    int  mi = (int)(key & 0xFFFFFFFFu);

    float success = (d < 2.5e-5f) ? 1.0f : 0.0f;   // RADIUS^2
    g_pos[q]  = success;
    g_wlab[q] = pcw[(size_t)b*MM + mi];
    float r = threefry_uniform_8192((unsigned)q);
    g_pri[q] = (success > 0.5f) ? __int_as_float(0x7f800000) : r;

    if (success > 0.5f){
      float Rm[9], Tv[3];
      const float* rp = pcr + ((size_t)b*MM + mi)*9;
#pragma unroll
      for (int u = 0; u < 9; u++) Rm[u] = rp[u];
      const float* tp = pct + ((size_t)b*MM + mi)*3;
      Tv[0]=tp[0]; Tv[1]=tp[1]; Tv[2]=tp[2];

      float gn = 0.0f, gsn = 0.0f;
#pragma unroll
      for (int c = 0; c < 5; c++){
#pragma unroll
        for (int d2 = 0; d2 < 3; d2++){
          float v  = Rm[d2*3+0]*s_cp [c*3+0] + Rm[d2*3+1]*s_cp [c*3+1] + Rm[d2*3+2]*s_cp [c*3+2] + Tv[d2];
          float vs = Rm[d2*3+0]*s_cps[c*3+0] + Rm[d2*3+1]*s_cps[c*3+1] + Rm[d2*3+2]*s_cps[c*3+2] + Tv[d2];
          gn  += v*v;
          gsn += vs*vs;
        }
      }
      unsigned slot = atomicAdd(&g_cnt[b], 1u);
      size_t ci = (size_t)b*NN + slot;
      g_cidx[ci] = q;
      float4* rec = g_crec + ci*4;
      rec[0] = make_float4(Rm[0], Rm[1], Rm[2], Tv[0]);
      rec[1] = make_float4(Rm[3], Rm[4], Rm[5], Tv[1]);
      rec[2] = make_float4(Rm[6], Rm[7], Rm[8], Tv[2]);
      rec[3] = make_float4(gn, gsn, 0.0f, 0.0f);
    }
  }
}

// ---------------- K2: ADD-S (Q=8/warp, barrier-free __ldg stream) + selection + finalize ----------------
__global__ __launch_bounds__(256, 1) void k_main(
    const float* __restrict__ grasps,
    const float* __restrict__ scores,
    const float* __restrict__ gwh,
    const float* __restrict__ cp,
    const float* __restrict__ cps,
    float* __restrict__ out, int out_size)
{
  __shared__ unsigned s_key[NN];               // sel role
  __shared__ unsigned s_hist[256];
  __shared__ unsigned s_bin, s_rem;
  __shared__ float    s_red[4][8];
  __shared__ float    s_cp[15], s_cps[15], s_part[8];
  __shared__ bool     s_isLast;

  int tid = threadIdx.x, lane = tid & 31, warp = tid >> 5;

  if (blockIdx.x < ADDS_BLOCKS){
    int b     = blockIdx.x >> 5;           // 32 blocks per batch
    int iBase = (blockIdx.x & 31)*64;
    int Npos  = (int)g_cnt[b];

    if (iBase < Npos){
      if (tid < 15){ s_cp[tid] = cp[tid]; s_cps[tid] = cps[tid]; }
      __syncthreads();

      int i0 = iBase + warp*8;
      bool v[8]; int orig[8];
      float A[8][9], As[8][9], T[8][3], pn[8];
#pragma unroll
      for (int q = 0; q < 8; q++){
        int slot = i0 + q;
        v[q] = (slot < Npos);
        int cs = v[q] ? slot : 0;
        orig[q] = g_cidx[(size_t)b*NN + cs];
        const float* gm = grasps + (size_t)orig[q]*16;
        float P[15];
        float pq = 0.0f;
#pragma unroll
        for (int c = 0; c < 5; c++)
#pragma unroll
          for (int d = 0; d < 3; d++){
            float vv = gm[d*4+0]*s_cp[c*3+0] + gm[d*4+1]*s_cp[c*3+1] + gm[d*4+2]*s_cp[c*3+2] + gm[d*4+3];
            P[c*3+d] = vv; pq += vv*vv;
          }
        pn[q] = pq;
#pragma unroll
        for (int d = 0; d < 3; d++){
          float s0=0, s1=0, s2=0, sp=0;
          float t0=0, t1=0, t2=0;
#pragma unroll
          for (int c = 0; c < 5; c++){
            float pv = P[c*3+d];
            s0 += pv*s_cp [c*3+0]; s1 += pv*s_cp [c*3+1]; s2 += pv*s_cp [c*3+2];
            t0 += pv*s_cps[c*3+0]; t1 += pv*s_cps[c*3+1]; t2 += pv*s_cps[c*3+2];
            sp += pv;
          }
          A [q][d*3+0]=s0; A [q][d*3+1]=s1; A [q][d*3+2]=s2;
          As[q][d*3+0]=t0; As[q][d*3+1]=t1; As[q][d*3+2]=t2;
          T [q][d]=sp;
        }
      }

      const float4* recs = g_crec + (size_t)b*NN*4;
      float m[8] = {3.4e38f,3.4e38f,3.4e38f,3.4e38f,3.4e38f,3.4e38f,3.4e38f,3.4e38f};
      for (int jj0 = 0; jj0 < Npos; jj0 += 32){
        int jj = jj0 + lane;
        bool jv = (jj < Npos);
        const float4* rp = recs + (size_t)(jv ? jj : 0)*4;
        float4 r0 = __ldg(rp+0);
        float4 r1 = __ldg(rp+1);
        float4 r2 = __ldg(rp+2);
        float4 r3 = __ldg(rp+3);
        if (!jv){ r3.x = 3.4e38f; r3.y = 3.4e38f; }
#pragma unroll
        for (int q = 0; q < 8; q++){
          float cT = fmaf(T[q][0], r0.w, fmaf(T[q][1], r1.w, T[q][2]*r2.w));
          float a0 = fmaf(A[q][0], r0.x, fmaf(A[q][1], r0.y, A[q][2]*r0.z));
          float a1 = fmaf(A[q][3], r1.x, fmaf(A[q][4], r1.y, A[q][5]*r1.z));
          float a2 = fmaf(A[q][6], r2.x, fmaf(A[q][7], r2.y, A[q][8]*r2.z));
          float b0 = fmaf(As[q][0], r0.x, fmaf(As[q][1], r0.y, As[q][2]*r0.z));
          float b1 = fmaf(As[q][3], r1.x, fmaf(As[q][4], r1.y, As[q][5]*r1.z));
          float b2 = fmaf(As[q][6], r2.x, fmaf(As[q][7], r2.y, As[q][8]*r2.z));
          float cA = (cT + a0) + (a1 + a2);
          float cS = (cT + b0) + (b1 + b2);
          float dG  = fmaf(-2.0f, cA, pn[q] + r3.x);
          float dGs = fmaf(-2.0f, cS, pn[q] + r3.y);
          m[q] = fminf(m[q], fminf(dG, dGs));
        }
      }
#pragma unroll
      for (int q = 0; q < 8; q++)
#pragma unroll
        for (int off = 16; off; off >>= 1)
          m[q] = fminf(m[q], __shfl_xor_sync(0xffffffffu, m[q], off));

      if (lane == 0){
        float contrib = 0.0f;
#pragma unroll
        for (int q = 0; q < 8; q++)
          if (v[q])
            contrib += sqrtf(fmaxf(m[q], 0.0f) + 1e-12f) * scores[orig[q]];
        s_part[warp] = contrib;
      }
      __syncthreads();
      if (tid == 0){
        double a = 0.0;
        for (int w = 0; w < 8; w++) a += (double)s_part[w];
        atomicAdd(&g_acc[b*8+4], a);
      }
    }
  } else {
    // ================= selection role: one block per batch =================
    int b = blockIdx.x - ADDS_BLOCKS;

    float possum = 0.0f;
    for (int i = tid; i < NN; i += 256){
      float pos = g_pos[(size_t)b*NN + i];
      float pri = g_pri[(size_t)b*NN + i];
      s_key[i] = (pos > 0.5f) ? 0xFFFFFFFFu : __float_as_uint(pri);
      possum += pos;
    }
#pragma unroll
    for (int off = 16; off; off >>= 1) possum += __shfl_xor_sync(0xffffffffu, possum, off);
    if (lane == 0) s_red[3][warp] = possum;
    __syncthreads();
    double nPos = 0.0;
    for (int w = 0; w < 8; w++) nPos += (double)s_red[3][w];
    unsigned kk = (nPos > 0.0) ? (unsigned)nPos : 2u;

    unsigned prefix = 0, prefmask = 0, krem = kk;
#pragma unroll
    for (int pass = 0; pass < 4; pass++){
      int shift = 24 - pass*8;
      s_hist[tid] = 0;
      __syncthreads();
      for (int i = tid; i < NN; i += 256){
        unsigned key = s_key[i];
        if ((key & prefmask) == prefix) atomicAdd(&s_hist[(key >> shift) & 0xFFu], 1u);
      }
      __syncthreads();
      if (tid < 32){
        unsigned loc[8]; unsigned tot = 0;
#pragma unroll
        for (int u = 0; u < 8; u++){ loc[u] = s_hist[tid*8+u]; tot += loc[u]; }
        unsigned sc = tot;
#pragma unroll
        for (int off = 1; off < 32; off <<= 1){
          unsigned vs = __shfl_up_sync(0xffffffffu, sc, off);
          if (lane >= off) sc += vs;
        }
        unsigned excl = sc - tot;
        bool has = (excl < krem) && (krem <= sc);
        unsigned msk = __ballot_sync(0xffffffffu, has);
        int src = __ffs(msk) - 1;
        if (tid == src){
          unsigned cum = excl; unsigned bin = tid*8;
#pragma unroll
          for (int u = 0; u < 8; u++){
            if (cum + loc[u] >= krem){ bin = tid*8+u; break; }
            cum += loc[u];
          }
          s_bin = bin; s_rem = krem - cum;
        }
      }
      __syncthreads();
      unsigned bin = s_bin;
      krem = s_rem;
      prefix |= bin << shift;
      prefmask |= 0xFFu << shift;
      __syncthreads();
    }
    unsigned t = prefix;
    unsigned rem = krem;   // ties at t to select (index order)

    float bcesum = 0.0f, selsum = 0.0f, wlsum = 0.0f;
    for (int i = tid; i < NN; i += 256){
      size_t gi = (size_t)b*NN + i;
      float pos = g_pos[gi];
      unsigned key = s_key[i];
      float sel;
      if (pos > 0.5f){
        sel = 1.0f;
      } else if (key < t){
        sel = 1.0f;
      } else if (key == t){
        unsigned tr = 0;
        for (int j = 0; j < i; j++) if (s_key[j] == t) tr++;
        sel = (tr < rem) ? 1.0f : 0.0f;
      } else {
        sel = 0.0f;
      }
      float p = scores[gi];
      p = fminf(fmaxf(p, 1e-7f), 1.0f - 1e-7f);
      float bce = -(pos*logf(p) + (1.0f - pos)*logf(1.0f - p));
      bcesum += bce*sel;
      selsum += sel;

      if (pos > 0.5f){
        float w = g_wlab[gi];
        float acc = 0.0f;
#pragma unroll
        for (int kb = 0; kb < 10; kb++){
          float mh = (w >= c_lo[kb] && w < c_hi[kb]) ? 1.0f : 0.0f;
          float x = gwh[(size_t)b*10*NN + (size_t)kb*NN + i];
          float bw = fmaxf(x, 0.0f) - x*mh + log1pf(expf(-fabsf(x)));
          acc += c_wt[kb]*bw;
        }
        wlsum += acc * 0.1f;
      }
    }
#pragma unroll
    for (int off = 16; off; off >>= 1){
      bcesum += __shfl_xor_sync(0xffffffffu, bcesum, off);
      selsum += __shfl_xor_sync(0xffffffffu, selsum, off);
      wlsum  += __shfl_xor_sync(0xffffffffu, wlsum , off);
    }
    if (lane == 0){ s_red[0][warp]=bcesum; s_red[1][warp]=selsum; s_red[2][warp]=wlsum; }
    __syncthreads();
    if (tid == 0){
      double a=0, c=0, d=0;
      for (int w = 0; w < 8; w++){ a += (double)s_red[0][w]; c += (double)s_red[1][w]; d += (double)s_red[2][w]; }
      g_acc[b*8+0] = nPos;
      g_acc[b*8+1] = a;
      g_acc[b*8+2] = c;
      g_acc[b*8+3] = d;
    }
  }

  // ---- last-block finalize (+ self-clean counters) ----
  __threadfence();
  __syncthreads();
  if (tid == 0){
    unsigned tk = atomicAdd(&g_ticket, 1u);
    s_isLast = (tk == MAIN_BLOCKS - 1u);
  }
  __syncthreads();
  if (s_isLast && tid == 0){
    __threadfence();
    volatile double* acc = g_acc;
    double bin = 0.0, wid = 0.0, adds = 0.0;
    for (int b = 0; b < BB; b++){
      double posSum = acc[b*8+0];
      double piv = fmax(posSum, 1.0);
      bin  += acc[b*8+1] / fmax(acc[b*8+2], 1.0);
      wid  += acc[b*8+3] / piv;
      adds += acc[b*8+4] / piv;
    }
    bin /= BB; wid /= BB; adds /= BB;
    double total = bin + wid + 3.0*adds;
    if (out_size > 0) out[0] = (float)total;
    if (out_size > 1) out[1] = (float)bin;
    if (out_size > 2) out[2] = (float)wid;
    if (out_size > 3) out[3] = (float)adds;
    // self-clean for next graph replay
    for (int b = 0; b < BB; b++){ g_acc[b*8+4] = 0.0; g_cnt[b] = 0u; }
    __threadfence();
    g_ticket = 0u;
  }
}

extern "C" void kernel_launch(void* const* d_in, const int* in_sizes, int n_in,
                              void* d_out, int out_size){
  const float* pred_grasps = (const float*)d_in[0];   // (4,2048,4,4)
  const float* pred_scores = (const float*)d_in[1];   // (4,2048,1)
  const float* pred_points = (const float*)d_in[2];   // (4,2048,3)
  const float* gwh         = (const float*)d_in[3];   // (4,10,2048)
  const float* pcp         = (const float*)d_in[4];   // (4,4096,3)
  const float* pcw         = (const float*)d_in[5];   // (4,4096)
  const float* pcr         = (const float*)d_in[6];   // (4,4096,3,3)
  const float* pct         = (const float*)d_in[7];   // (4,4096,3)
  const float* cp          = (const float*)d_in[8];   // (1,5,3)
  const float* cps         = (const float*)d_in[9];   // (1,5,3)

  k_nn1 <<<NQGROUP*NSPLIT, 256>>>(pred_points, pcp, pcw, pcr, pct, cp, cps);
  k_main<<<MAIN_BLOCKS, 256>>>(pred_grasps, pred_scores, gwh, cp, cps,
                               (float*)d_out, out_size);
}

// round 16
// speedup vs baseline: 1.2623x; 1.2623x over previous
// R16: R14/R15 experiments reverted — k_main = R12's proven smem-tile Q=4
// structure, with two inner-loop instruction cuts: cT seeds the a0/b0 FMA
// chains (saves 2 FADD/pair) and pn[q] hoisted out of the j-loop (added once
// after the warp reduction; argmin invariant). Rest byte-identical to R12.
#include <cuda_runtime.h>
#include <math.h>

#define BB 4
#define NN 2048
#define MM 4096
#define NSPLIT 4
#define MSPL (MM/NSPLIT)         // 1024 contacts per split
#define FARV 100000.0f
#define ADDS_BLOCKS 256          // 32 compacted queries per block (64 blocks/batch)
#define MAIN_BLOCKS (ADDS_BLOCKS + BB)
#define NQGROUP (BB*NN/32)       // 256 query groups of 32

typedef unsigned long long u64;

// ---------------- scratch (device globals; zero-init + self-cleaning) ----------------
__device__ u64      g_nnPart[BB*NN*NSPLIT]; // packed (d_bits<<32)|j partial argmins
__device__ float    g_pos[BB*NN];
__device__ float    g_pri[BB*NN];
__device__ float    g_wlab[BB*NN];
__device__ float4   g_crec[BB*NN*4];        // compacted positive records
__device__ int      g_cidx[BB*NN];          // compacted slot -> global query index
__device__ unsigned g_cnt[BB];              // positives per batch (reset by k_main finalize)
__device__ unsigned g_qtick[NQGROUP];       // per-qgroup tickets (reset by combiner)
__device__ double   g_acc[BB*8];            // 0 posSum,1 bceSum,2 selSum,3 wlSum, 4 addsSum(atomic)
__device__ unsigned g_ticket;               // k_main ticket (reset by finalize)

__constant__ float c_lo[10] = {0.0f, 0.00794435329f, 0.0158887021f, 0.0238330509f, 0.0317773996f,
                               0.0397217484f, 0.0476660972f, 0.0556104459f, 0.0635547947f, 0.0714991435f};
__constant__ float c_hi[10] = {0.00794435329f, 0.0158887021f, 0.0238330509f, 0.0317773996f, 0.0397217484f,
                               0.0476660972f, 0.0556104459f, 0.0635547947f, 0.0714991435f, 0.08f};
__constant__ float c_wt[10] = {0.16652107f, 0.21488856f, 0.37031708f, 0.55618503f, 0.75124664f,
                               0.93943357f, 1.07824539f, 1.19423112f, 1.55731375f, 2.34173634f};

// ---------------- threefry2x32 (JAX-exact, key(42), counts = iota(8192)) ----------------
__device__ __forceinline__ unsigned rotl32(unsigned x, unsigned d){ return (x<<d)|(x>>(32u-d)); }

__device__ __forceinline__ float threefry_uniform_8192(unsigned flat){
  unsigned c0, c1; bool second;
  if (flat < 4096u){ c0 = flat;        c1 = flat + 4096u; second = false; }
  else             { c0 = flat - 4096u; c1 = flat;        second = true;  }
  const unsigned ks0 = 0u, ks1 = 42u, ks2 = 0u ^ 42u ^ 0x1BD11BDAu;
  unsigned x0 = c0 + ks0, x1 = c1 + ks1;
#define TF_ROUND(r) { x0 += x1; x1 = rotl32(x1,(r)); x1 ^= x0; }
  TF_ROUND(13) TF_ROUND(15) TF_ROUND(26) TF_ROUND(6)
  x0 += ks1; x1 += ks2 + 1u;
  TF_ROUND(17) TF_ROUND(29) TF_ROUND(16) TF_ROUND(24)
  x0 += ks2; x1 += ks0 + 2u;
  TF_ROUND(13) TF_ROUND(15) TF_ROUND(26) TF_ROUND(6)
  x0 += ks0; x1 += ks1 + 3u;
  TF_ROUND(17) TF_ROUND(29) TF_ROUND(16) TF_ROUND(24)
  x0 += ks1; x1 += ks2 + 4u;
  TF_ROUND(13) TF_ROUND(15) TF_ROUND(26) TF_ROUND(6)
  x0 += ks2; x1 += ks0 + 5u;
#undef TF_ROUND
  unsigned bits = second ? x1 : x0;
  float f = __uint_as_float((bits >> 9) | 0x3F800000u) - 1.0f;
  return fmaxf(f, 0.0f);
}

// ---------------- K1: partial NN scan + last-block-per-qgroup combine ----------------
__global__ __launch_bounds__(256) void k_nn1(
    const float* __restrict__ pred_points,
    const float* __restrict__ pcp,
    const float* __restrict__ pcw,
    const float* __restrict__ pcr,
    const float* __restrict__ pct,
    const float* __restrict__ cp,
    const float* __restrict__ cps)
{
  __shared__ float4 s_pc[MSPL];     // (x,y,z, 0.5*|c|^2) 16KB
  __shared__ float  s_cp[15], s_cps[15];
  __shared__ bool   s_last;
  int tid = threadIdx.x, lane = tid & 31, warp = tid >> 5;
  int split  = blockIdx.x & (NSPLIT-1);
  int qgroup = blockIdx.x >> 2;
  int q0 = (qgroup*8 + warp)*4;
  int b  = q0 / NN;
  int jb = split*MSPL;

  {
    const float* base = pcp + ((size_t)b*MM + jb)*3;
    for (int j = tid; j < MSPL; j += 256){
      float x = base[j*3+0], y = base[j*3+1], z = base[j*3+2];
      s_pc[j] = make_float4(x, y, z, 0.5f*(x*x + y*y + z*z));
    }
  }
  __syncthreads();

  float nqx[4], nqy[4], nqz[4], qn[4];
#pragma unroll
  for (int k = 0; k < 4; k++){
    const float* p = pred_points + (size_t)(q0+k)*3;
    float px=p[0], py=p[1], pz=p[2];
    nqx[k]=-px; nqy[k]=-py; nqz[k]=-pz;
    qn[k]=px*px+py*py+pz*pz;
  }
  float beste[4] = {3.4e38f,3.4e38f,3.4e38f,3.4e38f};
  int   bidx[4] = {0,0,0,0};
  for (int j = lane; j < MSPL; j += 32){
    float4 c = s_pc[j];
#pragma unroll
    for (int k = 0; k < 4; k++){
      float e = fmaf(nqx[k], c.x, fmaf(nqy[k], c.y, fmaf(nqz[k], c.z, c.w)));
      if (e < beste[k]){ beste[k] = e; bidx[k] = j; }
    }
  }
#pragma unroll
  for (int k = 0; k < 4; k++){
    float d = fmaxf(fmaf(2.0f, beste[k], qn[k]), 0.0f);   // clamped distance
    u64 key = ((u64)__float_as_uint(d) << 32) | (unsigned)(jb + bidx[k]);
#pragma unroll
    for (int off = 16; off; off >>= 1){
      u64 o = __shfl_xor_sync(0xffffffffu, key, off);
      if (o < key) key = o;
    }
    if (lane == k) g_nnPart[(size_t)(q0+k)*NSPLIT + split] = key;
  }

  // ---- qgroup ticket: last of the NSPLIT blocks combines ----
  __threadfence();
  __syncthreads();
  if (tid == 0){
    unsigned tk = atomicAdd(&g_qtick[qgroup], 1u);
    s_last = (tk == NSPLIT - 1u);
  }
  __syncthreads();
  if (!s_last) return;
  __threadfence();   // acquire: see other blocks' partials

  if (tid < 15){ s_cp[tid] = cp[tid]; s_cps[tid] = cps[tid]; }
  if (tid == 0) g_qtick[qgroup] = 0u;   // self-clean for next call
  __syncthreads();

  if (tid < 32){
    int q = qgroup*32 + tid;
    const u64* part = g_nnPart + (size_t)q*NSPLIT;
    u64 key = part[0];
#pragma unroll
    for (int s = 1; s < NSPLIT; s++){ u64 o = part[s]; if (o < key) key = o; }
    float d = __uint_as_float((unsigned)(key >> 32));
    int  mi = (int)(key & 0xFFFFFFFFu);

    float success = (d < 2.5e-5f) ? 1.0f : 0.0f;   // RADIUS^2
    g_pos[q]  = success;
    g_wlab[q] = pcw[(size_t)b*MM + mi];
    float r = threefry_uniform_8192((unsigned)q);
    g_pri[q] = (success > 0.5f) ? __int_as_float(0x7f800000) : r;

    if (success > 0.5f){
      float Rm[9], Tv[3];
      const float* rp = pcr + ((size_t)b*MM + mi)*9;
#pragma unroll
      for (int u = 0; u < 9; u++) Rm[u] = rp[u];
      const float* tp = pct + ((size_t)b*MM + mi)*3;
      Tv[0]=tp[0]; Tv[1]=tp[1]; Tv[2]=tp[2];

      float gn = 0.0f, gsn = 0.0f;
#pragma unroll
      for (int c = 0; c < 5; c++){
#pragma unroll
        for (int d2 = 0; d2 < 3; d2++){
          float v  = Rm[d2*3+0]*s_cp [c*3+0] + Rm[d2*3+1]*s_cp [c*3+1] + Rm[d2*3+2]*s_cp [c*3+2] + Tv[d2];
          float vs = Rm[d2*3+0]*s_cps[c*3+0] + Rm[d2*3+1]*s_cps[c*3+1] + Rm[d2*3+2]*s_cps[c*3+2] + Tv[d2];
          gn  += v*v;
          gsn += vs*vs;
        }
      }
      unsigned slot = atomicAdd(&g_cnt[b], 1u);
      size_t ci = (size_t)b*NN + slot;
      g_cidx[ci] = q;
      float4* rec = g_crec + ci*4;
      rec[0] = make_float4(Rm[0], Rm[1], Rm[2], Tv[0]);
      rec[1] = make_float4(Rm[3], Rm[4], Rm[5], Tv[1]);
      rec[2] = make_float4(Rm[6], Rm[7], Rm[8], Tv[2]);
      rec[3] = make_float4(gn, gsn, 0.0f, 0.0f);
    }
  }
}

// ---------------- K2: ADD-S (Q=4/warp, smem tile) + selection + finalize ----------------
#define JT 256
__global__ __launch_bounds__(256, 2) void k_main(
    const float* __restrict__ grasps,
    const float* __restrict__ scores,
    const float* __restrict__ gwh,
    const float* __restrict__ cp,
    const float* __restrict__ cps,
    float* __restrict__ out, int out_size)
{
  __shared__ union {
    float4 tile[JT*5];                          // adds role: 20KB
    struct { unsigned key[NN]; unsigned hist[256]; } sel;  // sel role: 9KB
  } sm;
  __shared__ unsigned s_bin, s_rem;
  __shared__ float    s_red[4][8];
  __shared__ float    s_cp[15], s_cps[15], s_part[8];
  __shared__ bool     s_isLast;

  int tid = threadIdx.x, lane = tid & 31, warp = tid >> 5;

  if (blockIdx.x < ADDS_BLOCKS){
    int b     = blockIdx.x >> 6;           // 64 blocks per batch
    int iBase = (blockIdx.x & 63)*32;
    int Npos  = (int)g_cnt[b];

    if (iBase < Npos){
      if (tid < 15){ s_cp[tid] = cp[tid]; s_cps[tid] = cps[tid]; }
      __syncthreads();

      int i0 = iBase + warp*4;
      bool v[4]; int orig[4];
      float A[4][9], As[4][9], T[4][3], pn[4];
#pragma unroll
      for (int q = 0; q < 4; q++){
        int slot = i0 + q;
        v[q] = (slot < Npos);
        int cs = v[q] ? slot : 0;
        orig[q] = g_cidx[(size_t)b*NN + cs];
        const float* gm = grasps + (size_t)orig[q]*16;
        float P[15];
        float pq = 0.0f;
#pragma unroll
        for (int c = 0; c < 5; c++)
#pragma unroll
          for (int d = 0; d < 3; d++){
            float vv = gm[d*4+0]*s_cp[c*3+0] + gm[d*4+1]*s_cp[c*3+1] + gm[d*4+2]*s_cp[c*3+2] + gm[d*4+3];
            P[c*3+d] = vv; pq += vv*vv;
          }
        pn[q] = pq;
#pragma unroll
        for (int d = 0; d < 3; d++){
          float s0=0, s1=0, s2=0, sp=0;
          float t0=0, t1=0, t2=0;
#pragma unroll
          for (int c = 0; c < 5; c++){
            float pv = P[c*3+d];
            s0 += pv*s_cp [c*3+0]; s1 += pv*s_cp [c*3+1]; s2 += pv*s_cp [c*3+2];
            t0 += pv*s_cps[c*3+0]; t1 += pv*s_cps[c*3+1]; t2 += pv*s_cps[c*3+2];
            sp += pv;
          }
          A [q][d*3+0]=s0; A [q][d*3+1]=s1; A [q][d*3+2]=s2;
          As[q][d*3+0]=t0; As[q][d*3+1]=t1; As[q][d*3+2]=t2;
          T [q][d]=sp;
        }
      }

      // m tracks min_j (gn - 2*cross); pn added after the reduction.
      float m[4] = {3.4e38f, 3.4e38f, 3.4e38f, 3.4e38f};
      int ntile = (Npos + JT - 1)/JT;
      for (int t = 0; t < ntile; t++){
        __syncthreads();
        int jb = t*JT;
        for (int u = tid; u < JT*4; u += 256){
          int slotj = jb + (u>>2);
          float4 val;
          if (slotj < Npos) val = g_crec[((size_t)b*NN + slotj)*4 + (u&3)];
          else              val = ((u&3)==3) ? make_float4(3.4e38f,3.4e38f,0.f,0.f)
                                             : make_float4(0.f,0.f,0.f,0.f);
          sm.tile[(u>>2)*5 + (u&3)] = val;
        }
        __syncthreads();
#pragma unroll
        for (int u = 0; u < JT/32; u++){
          int jj = lane + u*32;
          float4 r0 = sm.tile[jj*5+0];
          float4 r1 = sm.tile[jj*5+1];
          float4 r2 = sm.tile[jj*5+2];
          float4 r3 = sm.tile[jj*5+3];
#pragma unroll
          for (int q = 0; q < 4; q++){
            float cT = fmaf(T[q][0], r0.w, fmaf(T[q][1], r1.w, T[q][2]*r2.w));
            // a0/b0 chains seeded with cT (saves one FADD each)
            float a0 = fmaf(A[q][0], r0.x, fmaf(A[q][1], r0.y, fmaf(A[q][2], r0.z, cT)));
            float a1 = fmaf(A[q][3], r1.x, fmaf(A[q][4], r1.y, A[q][5]*r1.z));
            float a2 = fmaf(A[q][6], r2.x, fmaf(A[q][7], r2.y, A[q][8]*r2.z));
            float b0 = fmaf(As[q][0], r0.x, fmaf(As[q][1], r0.y, fmaf(As[q][2], r0.z, cT)));
            float b1 = fmaf(As[q][3], r1.x, fmaf(As[q][4], r1.y, As[q][5]*r1.z));
            float b2 = fmaf(As[q][6], r2.x, fmaf(As[q][7], r2.y, As[q][8]*r2.z));
            float cA = a0 + (a1 + a2);
            float cS = b0 + (b1 + b2);
            // pn hoisted out: dG' = gn - 2*cA
            float dG  = fmaf(-2.0f, cA, r3.x);
            float dGs = fmaf(-2.0f, cS, r3.y);
            m[q] = fminf(m[q], fminf(dG, dGs));
          }
        }
      }
#pragma unroll
      for (int q = 0; q < 4; q++)
#pragma unroll
        for (int off = 16; off; off >>= 1)
          m[q] = fminf(m[q], __shfl_xor_sync(0xffffffffu, m[q], off));

      if (lane == 0){
        float contrib = 0.0f;
#pragma unroll
        for (int q = 0; q < 4; q++)
          if (v[q])
            contrib += sqrtf(fmaxf(pn[q] + m[q], 0.0f) + 1e-12f) * scores[orig[q]];
        s_part[warp] = contrib;
      }
      __syncthreads();
      if (tid == 0){
        double a = 0.0;
        for (int w = 0; w < 8; w++) a += (double)s_part[w];
        atomicAdd(&g_acc[b*8+4], a);
      }
    }
  } else {
    // ================= selection role: one block per batch =================
    int b = blockIdx.x - ADDS_BLOCKS;

    float possum = 0.0f;
    for (int i = tid; i < NN; i += 256){
      float pos = g_pos[(size_t)b*NN + i];
      float pri = g_pri[(size_t)b*NN + i];
      sm.sel.key[i] = (pos > 0.5f) ? 0xFFFFFFFFu : __float_as_uint(pri);
      possum += pos;
    }
#pragma unroll
    for (int off = 16; off; off >>= 1) possum += __shfl_xor_sync(0xffffffffu, possum, off);
    if (lane == 0) s_red[3][warp] = possum;
    __syncthreads();
    double nPos = 0.0;
    for (int w = 0; w < 8; w++) nPos += (double)s_red[3][w];
    unsigned kk = (nPos > 0.0) ? (unsigned)nPos : 2u;

    unsigned prefix = 0, prefmask = 0, krem = kk;
#pragma unroll
    for (int pass = 0; pass < 4; pass++){
      int shift = 24 - pass*8;
      sm.sel.hist[tid] = 0;
      __syncthreads();
      for (int i = tid; i < NN; i += 256){
        unsigned key = sm.sel.key[i];
        if ((key & prefmask) == prefix) atomicAdd(&sm.sel.hist[(key >> shift) & 0xFFu], 1u);
      }
      __syncthreads();
      if (tid < 32){
        unsigned loc[8]; unsigned tot = 0;
#pragma unroll
        for (int u = 0; u < 8; u++){ loc[u] = sm.sel.hist[tid*8+u]; tot += loc[u]; }
        unsigned sc = tot;
#pragma unroll
        for (int off = 1; off < 32; off <<= 1){
          unsigned vs = __shfl_up_sync(0xffffffffu, sc, off);
          if (lane >= off) sc += vs;
        }
        unsigned excl = sc - tot;
        bool has = (excl < krem) && (krem <= sc);
        unsigned msk = __ballot_sync(0xffffffffu, has);
        int src = __ffs(msk) - 1;
        if (tid == src){
          unsigned cum = excl; unsigned bin = tid*8;
#pragma unroll
          for (int u = 0; u < 8; u++){
            if (cum + loc[u] >= krem){ bin = tid*8+u; break; }
            cum += loc[u];
          }
          s_bin = bin; s_rem = krem - cum;
        }
      }
      __syncthreads();
      unsigned bin = s_bin;
      krem = s_rem;
      prefix |= bin << shift;
      prefmask |= 0xFFu << shift;
      __syncthreads();
    }
    unsigned t = prefix;
    unsigned rem = krem;   // ties at t to select (index order)

    float bcesum = 0.0f, selsum = 0.0f, wlsum = 0.0f;
    for (int i = tid; i < NN; i += 256){
      size_t gi = (size_t)b*NN + i;
      float pos = g_pos[gi];
      unsigned key = sm.sel.key[i];
      float sel;
      if (pos > 0.5f){
        sel = 1.0f;
      } else if (key < t){
        sel = 1.0f;
      } else if (key == t){
        unsigned tr = 0;
        for (int j = 0; j < i; j++) if (sm.sel.key[j] == t) tr++;
        sel = (tr < rem) ? 1.0f : 0.0f;
      } else {
        sel = 0.0f;
      }
      float p = scores[gi];
      p = fminf(fmaxf(p, 1e-7f), 1.0f - 1e-7f);
      float bce = -(pos*logf(p) + (1.0f - pos)*logf(1.0f - p));
      bcesum += bce*sel;
      selsum += sel;

      if (pos > 0.5f){
        float w = g_wlab[gi];
        float acc = 0.0f;
#pragma unroll
        for (int kb = 0; kb < 10; kb++){
          float mh = (w >= c_lo[kb] && w < c_hi[kb]) ? 1.0f : 0.0f;
          float x = gwh[(size_t)b*10*NN + (size_t)kb*NN + i];
          float bw = fmaxf(x, 0.0f) - x*mh + log1pf(expf(-fabsf(x)));
          acc += c_wt[kb]*bw;
        }
        wlsum += acc * 0.1f;
      }
    }
#pragma unroll
    for (int off = 16; off; off >>= 1){
      bcesum += __shfl_xor_sync(0xffffffffu, bcesum, off);
      selsum += __shfl_xor_sync(0xffffffffu, selsum, off);
      wlsum  += __shfl_xor_sync(0xffffffffu, wlsum , off);
    }
    if (lane == 0){ s_red[0][warp]=bcesum; s_red[1][warp]=selsum; s_red[2][warp]=wlsum; }
    __syncthreads();
    if (tid == 0){
      double a=0, c=0, d=0;
      for (int w = 0; w < 8; w++){ a += (double)s_red[0][w]; c += (double)s_red[1][w]; d += (double)s_red[2][w]; }
      g_acc[b*8+0] = nPos;
      g_acc[b*8+1] = a;
      g_acc[b*8+2] = c;
      g_acc[b*8+3] = d;
    }
  }

  // ---- last-block finalize (+ self-clean counters) ----
  __threadfence();
  __syncthreads();
  if (tid == 0){
    unsigned tk = atomicAdd(&g_ticket, 1u);
    s_isLast = (tk == MAIN_BLOCKS - 1u);
  }
  __syncthreads();
  if (s_isLast && tid == 0){
    __threadfence();
    volatile double* acc = g_acc;
    double bin = 0.0, wid = 0.0, adds = 0.0;
    for (int b = 0; b < BB; b++){
      double posSum = acc[b*8+0];
      double piv = fmax(posSum, 1.0);
      bin  += acc[b*8+1] / fmax(acc[b*8+2], 1.0);
      wid  += acc[b*8+3] / piv;
      adds += acc[b*8+4] / piv;
    }
    bin /= BB; wid /= BB; adds /= BB;
    double total = bin + wid + 3.0*adds;
    if (out_size > 0) out[0] = (float)total;
    if (out_size > 1) out[1] = (float)bin;
    if (out_size > 2) out[2] = (float)wid;
    if (out_size > 3) out[3] = (float)adds;
    // self-clean for next graph replay
    for (int b = 0; b < BB; b++){ g_acc[b*8+4] = 0.0; g_cnt[b] = 0u; }
    __threadfence();
    g_ticket = 0u;
  }
}

extern "C" void kernel_launch(void* const* d_in, const int* in_sizes, int n_in,
                              void* d_out, int out_size){
  const float* pred_grasps = (const float*)d_in[0];   // (4,2048,4,4)
  const float* pred_scores = (const float*)d_in[1];   // (4,2048,1)
  const float* pred_points = (const float*)d_in[2];   // (4,2048,3)
  const float* gwh         = (const float*)d_in[3];   // (4,10,2048)
  const float* pcp         = (const float*)d_in[4];   // (4,4096,3)
  const float* pcw         = (const float*)d_in[5];   // (4,4096)
  const float* pcr         = (const float*)d_in[6];   // (4,4096,3,3)
  const float* pct         = (const float*)d_in[7];   // (4,4096,3)
  const float* cp          = (const float*)d_in[8];   // (1,5,3)
  const float* cps         = (const float*)d_in[9];   // (1,5,3)

  k_nn1 <<<NQGROUP*NSPLIT, 256>>>(pred_points, pcp, pcw, pcr, pct, cp, cps);
  k_main<<<MAIN_BLOCKS, 256>>>(pred_grasps, pred_scores, gwh, cp, cps,
                               (float*)d_out, out_size);
}

// round 17
// speedup vs baseline: 1.3199x; 1.0456x over previous
// R17: exact j-record dedup for ADD-S — records are keyed by nearest-contact
// index mi, so duplicates (queries sharing a nearest contact, ~19% of the set)
// are inserted once via g_seen[b][mi] atomicExch. i-list (all positives) and
// j-list (distinct records) now separate counters. g_seen reset at k_main
// block start (safe: consumed by this call's k_nn1 already). Inner loops,
// sel, finalize byte-identical to R16.
#include <cuda_runtime.h>
#include <math.h>

#define BB 4
#define NN 2048
#define MM 4096
#define NSPLIT 4
#define MSPL (MM/NSPLIT)         // 1024 contacts per split
#define FARV 100000.0f
#define ADDS_BLOCKS 256          // 32 i-queries per block (64 blocks/batch)
#define MAIN_BLOCKS (ADDS_BLOCKS + BB)
#define NQGROUP (BB*NN/32)       // 256 query groups of 32

typedef unsigned long long u64;

// ---------------- scratch (device globals; zero-init + self-cleaning) ----------------
__device__ u64      g_nnPart[BB*NN*NSPLIT]; // packed (d_bits<<32)|j partial argmins
__device__ float    g_pos[BB*NN];
__device__ float    g_pri[BB*NN];
__device__ float    g_wlab[BB*NN];
__device__ float4   g_crec[BB*NN*4];        // dedup'd positive records
__device__ int      g_cidx[BB*NN];          // i-slot -> global query index
__device__ unsigned g_icnt[BB];             // positives per batch (reset by finalize)
__device__ unsigned g_jcnt[BB];             // distinct records per batch (reset by finalize)
__device__ unsigned g_seen[BB*MM];          // per-(b,mi) claim flags (reset by k_main start)
__device__ unsigned g_qtick[NQGROUP];       // per-qgroup tickets (reset by combiner)
__device__ double   g_acc[BB*8];            // 0 posSum,1 bceSum,2 selSum,3 wlSum, 4 addsSum(atomic)
__device__ unsigned g_ticket;               // k_main ticket (reset by finalize)

__constant__ float c_lo[10] = {0.0f, 0.00794435329f, 0.0158887021f, 0.0238330509f, 0.0317773996f,
                               0.0397217484f, 0.0476660972f, 0.0556104459f, 0.0635547947f, 0.0714991435f};
__constant__ float c_hi[10] = {0.00794435329f, 0.0158887021f, 0.0238330509f, 0.0317773996f, 0.0397217484f,
                               0.0476660972f, 0.0556104459f, 0.0635547947f, 0.0714991435f, 0.08f};
__constant__ float c_wt[10] = {0.16652107f, 0.21488856f, 0.37031708f, 0.55618503f, 0.75124664f,
                               0.93943357f, 1.07824539f, 1.19423112f, 1.55731375f, 2.34173634f};

// ---------------- threefry2x32 (JAX-exact, key(42), counts = iota(8192)) ----------------
__device__ __forceinline__ unsigned rotl32(unsigned x, unsigned d){ return (x<<d)|(x>>(32u-d)); }

__device__ __forceinline__ float threefry_uniform_8192(unsigned flat){
  unsigned c0, c1; bool second;
  if (flat < 4096u){ c0 = flat;        c1 = flat + 4096u; second = false; }
  else             { c0 = flat - 4096u; c1 = flat;        second = true;  }
  const unsigned ks0 = 0u, ks1 = 42u, ks2 = 0u ^ 42u ^ 0x1BD11BDAu;
  unsigned x0 = c0 + ks0, x1 = c1 + ks1;
#define TF_ROUND(r) { x0 += x1; x1 = rotl32(x1,(r)); x1 ^= x0; }
  TF_ROUND(13) TF_ROUND(15) TF_ROUND(26) TF_ROUND(6)
  x0 += ks1; x1 += ks2 + 1u;
  TF_ROUND(17) TF_ROUND(29) TF_ROUND(16) TF_ROUND(24)
  x0 += ks2; x1 += ks0 + 2u;
  TF_ROUND(13) TF_ROUND(15) TF_ROUND(26) TF_ROUND(6)
  x0 += ks0; x1 += ks1 + 3u;
  TF_ROUND(17) TF_ROUND(29) TF_ROUND(16) TF_ROUND(24)
  x0 += ks1; x1 += ks2 + 4u;
  TF_ROUND(13) TF_ROUND(15) TF_ROUND(26) TF_ROUND(6)
  x0 += ks2; x1 += ks0 + 5u;
#undef TF_ROUND
  unsigned bits = second ? x1 : x0;
  float f = __uint_as_float((bits >> 9) | 0x3F800000u) - 1.0f;
  return fmaxf(f, 0.0f);
}

// ---------------- K1: partial NN scan + last-block-per-qgroup combine ----------------
__global__ __launch_bounds__(256) void k_nn1(
    const float* __restrict__ pred_points,
    const float* __restrict__ pcp,
    const float* __restrict__ pcw,
    const float* __restrict__ pcr,
    const float* __restrict__ pct,
    const float* __restrict__ cp,
    const float* __restrict__ cps)
{
  __shared__ float4 s_pc[MSPL];     // (x,y,z, 0.5*|c|^2) 16KB
  __shared__ float  s_cp[15], s_cps[15];
  __shared__ bool   s_last;
  int tid = threadIdx.x, lane = tid & 31, warp = tid >> 5;
  int split  = blockIdx.x & (NSPLIT-1);
  int qgroup = blockIdx.x >> 2;
  int q0 = (qgroup*8 + warp)*4;
  int b  = q0 / NN;
  int jb = split*MSPL;

  {
    const float* base = pcp + ((size_t)b*MM + jb)*3;
    for (int j = tid; j < MSPL; j += 256){
      float x = base[j*3+0], y = base[j*3+1], z = base[j*3+2];
      s_pc[j] = make_float4(x, y, z, 0.5f*(x*x + y*y + z*z));
    }
  }
  __syncthreads();

  float nqx[4], nqy[4], nqz[4], qn[4];
#pragma unroll
  for (int k = 0; k < 4; k++){
    const float* p = pred_points + (size_t)(q0+k)*3;
    float px=p[0], py=p[1], pz=p[2];
    nqx[k]=-px; nqy[k]=-py; nqz[k]=-pz;
    qn[k]=px*px+py*py+pz*pz;
  }
  float beste[4] = {3.4e38f,3.4e38f,3.4e38f,3.4e38f};
  int   bidx[4] = {0,0,0,0};
  for (int j = lane; j < MSPL; j += 32){
    float4 c = s_pc[j];
#pragma unroll
    for (int k = 0; k < 4; k++){
      float e = fmaf(nqx[k], c.x, fmaf(nqy[k], c.y, fmaf(nqz[k], c.z, c.w)));
      if (e < beste[k]){ beste[k] = e; bidx[k] = j; }
    }
  }
#pragma unroll
  for (int k = 0; k < 4; k++){
    float d = fmaxf(fmaf(2.0f, beste[k], qn[k]), 0.0f);   // clamped distance
    u64 key = ((u64)__float_as_uint(d) << 32) | (unsigned)(jb + bidx[k]);
#pragma unroll
    for (int off = 16; off; off >>= 1){
      u64 o = __shfl_xor_sync(0xffffffffu, key, off);
      if (o < key) key = o;
    }
    if (lane == k) g_nnPart[(size_t)(q0+k)*NSPLIT + split] = key;
  }

  // ---- qgroup ticket: last of the NSPLIT blocks combines ----
  __threadfence();
  __syncthreads();
  if (tid == 0){
    unsigned tk = atomicAdd(&g_qtick[qgroup], 1u);
    s_last = (tk == NSPLIT - 1u);
  }
  __syncthreads();
  if (!s_last) return;
  __threadfence();   // acquire: see other blocks' partials

  if (tid < 15){ s_cp[tid] = cp[tid]; s_cps[tid] = cps[tid]; }
  if (tid == 0) g_qtick[qgroup] = 0u;   // self-clean for next call
  __syncthreads();

  if (tid < 32){
    int q = qgroup*32 + tid;
    const u64* part = g_nnPart + (size_t)q*NSPLIT;
    u64 key = part[0];
#pragma unroll
    for (int s = 1; s < NSPLIT; s++){ u64 o = part[s]; if (o < key) key = o; }
    float d = __uint_as_float((unsigned)(key >> 32));
    int  mi = (int)(key & 0xFFFFFFFFu);

    float success = (d < 2.5e-5f) ? 1.0f : 0.0f;   // RADIUS^2
    g_pos[q]  = success;
    g_wlab[q] = pcw[(size_t)b*MM + mi];
    float r = threefry_uniform_8192((unsigned)q);
    g_pri[q] = (success > 0.5f) ? __int_as_float(0x7f800000) : r;

    if (success > 0.5f){
      // i-list: every positive query
      unsigned iSlot = atomicAdd(&g_icnt[b], 1u);
      g_cidx[(size_t)b*NN + iSlot] = q;
      // j-list: only the first claimant of (b, mi) inserts the record
      unsigned old = atomicExch(&g_seen[(size_t)b*MM + mi], 1u);
      if (old == 0u){
        float Rm[9], Tv[3];
        const float* rp = pcr + ((size_t)b*MM + mi)*9;
#pragma unroll
        for (int u = 0; u < 9; u++) Rm[u] = rp[u];
        const float* tp = pct + ((size_t)b*MM + mi)*3;
        Tv[0]=tp[0]; Tv[1]=tp[1]; Tv[2]=tp[2];

        float gn = 0.0f, gsn = 0.0f;
#pragma unroll
        for (int c = 0; c < 5; c++){
#pragma unroll
          for (int d2 = 0; d2 < 3; d2++){
            float v  = Rm[d2*3+0]*s_cp [c*3+0] + Rm[d2*3+1]*s_cp [c*3+1] + Rm[d2*3+2]*s_cp [c*3+2] + Tv[d2];
            float vs = Rm[d2*3+0]*s_cps[c*3+0] + Rm[d2*3+1]*s_cps[c*3+1] + Rm[d2*3+2]*s_cps[c*3+2] + Tv[d2];
            gn  += v*v;
            gsn += vs*vs;
          }
        }
        unsigned jSlot = atomicAdd(&g_jcnt[b], 1u);
        size_t ci = (size_t)b*NN + jSlot;
        float4* rec = g_crec + ci*4;
        rec[0] = make_float4(Rm[0], Rm[1], Rm[2], Tv[0]);
        rec[1] = make_float4(Rm[3], Rm[4], Rm[5], Tv[1]);
        rec[2] = make_float4(Rm[6], Rm[7], Rm[8], Tv[2]);
        rec[3] = make_float4(gn, gsn, 0.0f, 0.0f);
      }
    }
  }
}

// ---------------- K2: ADD-S (Q=4/warp, smem tile, dedup'd j) + selection + finalize ----------------
#define JT 256
__global__ __launch_bounds__(256, 2) void k_main(
    const float* __restrict__ grasps,
    const float* __restrict__ scores,
    const float* __restrict__ gwh,
    const float* __restrict__ cp,
    const float* __restrict__ cps,
    float* __restrict__ out, int out_size)
{
  __shared__ union {
    float4 tile[JT*5];                          // adds role: 20KB
    struct { unsigned key[NN]; unsigned hist[256]; } sel;  // sel role: 9KB
  } sm;
  __shared__ unsigned s_bin, s_rem;
  __shared__ float    s_red[4][8];
  __shared__ float    s_cp[15], s_cps[15], s_part[8];
  __shared__ bool     s_isLast;

  int tid = threadIdx.x, lane = tid & 31, warp = tid >> 5;

  // reset g_seen for the NEXT call (this call's k_nn1 already consumed it)
  {
    int ridx = blockIdx.x*256 + tid;
    if (ridx < BB*MM) g_seen[ridx] = 0u;
  }

  if (blockIdx.x < ADDS_BLOCKS){
    int b     = blockIdx.x >> 6;           // 64 blocks per batch
    int iBase = (blockIdx.x & 63)*32;
    int Nq    = (int)g_icnt[b];
    int Nj    = (int)g_jcnt[b];

    if (iBase < Nq){
      if (tid < 15){ s_cp[tid] = cp[tid]; s_cps[tid] = cps[tid]; }
      __syncthreads();

      int i0 = iBase + warp*4;
      bool v[4]; int orig[4];
      float A[4][9], As[4][9], T[4][3], pn[4];
#pragma unroll
      for (int q = 0; q < 4; q++){
        int slot = i0 + q;
        v[q] = (slot < Nq);
        int cs = v[q] ? slot : 0;
        orig[q] = g_cidx[(size_t)b*NN + cs];
        const float* gm = grasps + (size_t)orig[q]*16;
        float P[15];
        float pq = 0.0f;
#pragma unroll
        for (int c = 0; c < 5; c++)
#pragma unroll
          for (int d = 0; d < 3; d++){
            float vv = gm[d*4+0]*s_cp[c*3+0] + gm[d*4+1]*s_cp[c*3+1] + gm[d*4+2]*s_cp[c*3+2] + gm[d*4+3];
            P[c*3+d] = vv; pq += vv*vv;
          }
        pn[q] = pq;
#pragma unroll
        for (int d = 0; d < 3; d++){
          float s0=0, s1=0, s2=0, sp=0;
          float t0=0, t1=0, t2=0;
#pragma unroll
          for (int c = 0; c < 5; c++){
            float pv = P[c*3+d];
            s0 += pv*s_cp [c*3+0]; s1 += pv*s_cp [c*3+1]; s2 += pv*s_cp [c*3+2];
            t0 += pv*s_cps[c*3+0]; t1 += pv*s_cps[c*3+1]; t2 += pv*s_cps[c*3+2];
            sp += pv;
          }
          A [q][d*3+0]=s0; A [q][d*3+1]=s1; A [q][d*3+2]=s2;
          As[q][d*3+0]=t0; As[q][d*3+1]=t1; As[q][d*3+2]=t2;
          T [q][d]=sp;
        }
      }

      // m tracks min_j (gn - 2*cross); pn added after the reduction.
      float m[4] = {3.4e38f, 3.4e38f, 3.4e38f, 3.4e38f};
      int ntile = (Nj + JT - 1)/JT;
      for (int t = 0; t < ntile; t++){
        __syncthreads();
        int jb = t*JT;
        for (int u = tid; u < JT*4; u += 256){
          int slotj = jb + (u>>2);
          float4 val;
          if (slotj < Nj) val = g_crec[((size_t)b*NN + slotj)*4 + (u&3)];
          else            val = ((u&3)==3) ? make_float4(3.4e38f,3.4e38f,0.f,0.f)
                                           : make_float4(0.f,0.f,0.f,0.f);
          sm.tile[(u>>2)*5 + (u&3)] = val;
        }
        __syncthreads();
#pragma unroll
        for (int u = 0; u < JT/32; u++){
          int jj = lane + u*32;
          float4 r0 = sm.tile[jj*5+0];
          float4 r1 = sm.tile[jj*5+1];
          float4 r2 = sm.tile[jj*5+2];
          float4 r3 = sm.tile[jj*5+3];
#pragma unroll
          for (int q = 0; q < 4; q++){
            float cT = fmaf(T[q][0], r0.w, fmaf(T[q][1], r1.w, T[q][2]*r2.w));
            float a0 = fmaf(A[q][0], r0.x, fmaf(A[q][1], r0.y, fmaf(A[q][2], r0.z, cT)));
            float a1 = fmaf(A[q][3], r1.x, fmaf(A[q][4], r1.y, A[q][5]*r1.z));
            float a2 = fmaf(A[q][6], r2.x, fmaf(A[q][7], r2.y, A[q][8]*r2.z));
            float b0 = fmaf(As[q][0], r0.x, fmaf(As[q][1], r0.y, fmaf(As[q][2], r0.z, cT)));
            float b1 = fmaf(As[q][3], r1.x, fmaf(As[q][4], r1.y, As[q][5]*r1.z));
            float b2 = fmaf(As[q][6], r2.x, fmaf(As[q][7], r2.y, As[q][8]*r2.z));
            float cA = a0 + (a1 + a2);
            float cS = b0 + (b1 + b2);
            float dG  = fmaf(-2.0f, cA, r3.x);
            float dGs = fmaf(-2.0f, cS, r3.y);
            m[q] = fminf(m[q], fminf(dG, dGs));
          }
        }
      }
#pragma unroll
      for (int q = 0; q < 4; q++)
#pragma unroll
        for (int off = 16; off; off >>= 1)
          m[q] = fminf(m[q], __shfl_xor_sync(0xffffffffu, m[q], off));

      if (lane == 0){
        float contrib = 0.0f;
#pragma unroll
        for (int q = 0; q < 4; q++)
          if (v[q])
            contrib += sqrtf(fmaxf(pn[q] + m[q], 0.0f) + 1e-12f) * scores[orig[q]];
        s_part[warp] = contrib;
      }
      __syncthreads();
      if (tid == 0){
        double a = 0.0;
        for (int w = 0; w < 8; w++) a += (double)s_part[w];
        atomicAdd(&g_acc[b*8+4], a);
      }
    }
  } else {
    // ================= selection role: one block per batch =================
    int b = blockIdx.x - ADDS_BLOCKS;

    float possum = 0.0f;
    for (int i = tid; i < NN; i += 256){
      float pos = g_pos[(size_t)b*NN + i];
      float pri = g_pri[(size_t)b*NN + i];
      sm.sel.key[i] = (pos > 0.5f) ? 0xFFFFFFFFu : __float_as_uint(pri);
      possum += pos;
    }
#pragma unroll
    for (int off = 16; off; off >>= 1) possum += __shfl_xor_sync(0xffffffffu, possum, off);
    if (lane == 0) s_red[3][warp] = possum;
    __syncthreads();
    double nPos = 0.0;
    for (int w = 0; w < 8; w++) nPos += (double)s_red[3][w];
    unsigned kk = (nPos > 0.0) ? (unsigned)nPos : 2u;

    unsigned prefix = 0, prefmask = 0, krem = kk;
#pragma unroll
    for (int pass = 0; pass < 4; pass++){
      int shift = 24 - pass*8;
      sm.sel.hist[tid] = 0;
      __syncthreads();
      for (int i = tid; i < NN; i += 256){
        unsigned key = sm.sel.key[i];
        if ((key & prefmask) == prefix) atomicAdd(&sm.sel.hist[(key >> shift) & 0xFFu], 1u);
      }
      __syncthreads();
      if (tid < 32){
        unsigned loc[8]; unsigned tot = 0;
#pragma unroll
        for (int u = 0; u < 8; u++){ loc[u] = sm.sel.hist[tid*8+u]; tot += loc[u]; }
        unsigned sc = tot;
#pragma unroll
        for (int off = 1; off < 32; off <<= 1){
          unsigned vs = __shfl_up_sync(0xffffffffu, sc, off);
          if (lane >= off) sc += vs;
        }
        unsigned excl = sc - tot;
        bool has = (excl < krem) && (krem <= sc);
        unsigned msk = __ballot_sync(0xffffffffu, has);
        int src = __ffs(msk) - 1;
        if (tid == src){
          unsigned cum = excl; unsigned bin = tid*8;
#pragma unroll
          for (int u = 0; u < 8; u++){
            if (cum + loc[u] >= krem){ bin = tid*8+u; break; }
            cum += loc[u];
          }
          s_bin = bin; s_rem = krem - cum;
        }
      }
      __syncthreads();
      unsigned bin = s_bin;
      krem = s_rem;
      prefix |= bin << shift;
      prefmask |= 0xFFu << shift;
      __syncthreads();
    }
    unsigned t = prefix;
    unsigned rem = krem;   // ties at t to select (index order)

    float bcesum = 0.0f, selsum = 0.0f, wlsum = 0.0f;
    for (int i = tid; i < NN; i += 256){
      size_t gi = (size_t)b*NN + i;
      float pos = g_pos[gi];
      unsigned key = sm.sel.key[i];
      float sel;
      if (pos > 0.5f){
        sel = 1.0f;
      } else if (key < t){
        sel = 1.0f;
      } else if (key == t){
        unsigned tr = 0;
        for (int j = 0; j < i; j++) if (sm.sel.key[j] == t) tr++;
        sel = (tr < rem) ? 1.0f : 0.0f;
      } else {
        sel = 0.0f;
      }
      float p = scores[gi];
      p = fminf(fmaxf(p, 1e-7f), 1.0f - 1e-7f);
      float bce = -(pos*logf(p) + (1.0f - pos)*logf(1.0f - p));
      bcesum += bce*sel;
      selsum += sel;

      if (pos > 0.5f){
        float w = g_wlab[gi];
        float acc = 0.0f;
#pragma unroll
        for (int kb = 0; kb < 10; kb++){
          float mh = (w >= c_lo[kb] && w < c_hi[kb]) ? 1.0f : 0.0f;
          float x = gwh[(size_t)b*10*NN + (size_t)kb*NN + i];
          float bw = fmaxf(x, 0.0f) - x*mh + log1pf(expf(-fabsf(x)));
          acc += c_wt[kb]*bw;
        }
        wlsum += acc * 0.1f;
      }
    }
#pragma unroll
    for (int off = 16; off; off >>= 1){
      bcesum += __shfl_xor_sync(0xffffffffu, bcesum, off);
      selsum += __shfl_xor_sync(0xffffffffu, selsum, off);
      wlsum  += __shfl_xor_sync(0xffffffffu, wlsum , off);
    }
    if (lane == 0){ s_red[0][warp]=bcesum; s_red[1][warp]=selsum; s_red[2][warp]=wlsum; }
    __syncthreads();
    if (tid == 0){
      double a=0, c=0, d=0;
      for (int w = 0; w < 8; w++){ a += (double)s_red[0][w]; c += (double)s_red[1][w]; d += (double)s_red[2][w]; }
      g_acc[b*8+0] = nPos;
      g_acc[b*8+1] = a;
      g_acc[b*8+2] = c;
      g_acc[b*8+3] = d;
    }
  }

  // ---- last-block finalize (+ self-clean counters) ----
  __threadfence();
  __syncthreads();
  if (tid == 0){
    unsigned tk = atomicAdd(&g_ticket, 1u);
    s_isLast = (tk == MAIN_BLOCKS - 1u);
  }
  __syncthreads();
  if (s_isLast && tid == 0){
    __threadfence();
    volatile double* acc = g_acc;
    double bin = 0.0, wid = 0.0, adds = 0.0;
    for (int b = 0; b < BB; b++){
      double posSum = acc[b*8+0];
      double piv = fmax(posSum, 1.0);
      bin  += acc[b*8+1] / fmax(acc[b*8+2], 1.0);
      wid  += acc[b*8+3] / piv;
      adds += acc[b*8+4] / piv;
    }
    bin /= BB; wid /= BB; adds /= BB;
    double total = bin + wid + 3.0*adds;
    if (out_size > 0) out[0] = (float)total;
    if (out_size > 1) out[1] = (float)bin;
    if (out_size > 2) out[2] = (float)wid;
    if (out_size > 3) out[3] = (float)adds;
    // self-clean for next graph replay
    for (int b = 0; b < BB; b++){ g_acc[b*8+4] = 0.0; g_icnt[b] = 0u; g_jcnt[b] = 0u; }
    __threadfence();
    g_ticket = 0u;
  }
}

extern "C" void kernel_launch(void* const* d_in, const int* in_sizes, int n_in,
                              void* d_out, int out_size){
  const float* pred_grasps = (const float*)d_in[0];   // (4,2048,4,4)
  const float* pred_scores = (const float*)d_in[1];   // (4,2048,1)
  const float* pred_points = (const float*)d_in[2];   // (4,2048,3)
  const float* gwh         = (const float*)d_in[3];   // (4,10,2048)
  const float* pcp         = (const float*)d_in[4];   // (4,4096,3)
  const float* pcw         = (const float*)d_in[5];   // (4,4096)
  const float* pcr         = (const float*)d_in[6];   // (4,4096,3,3)
  const float* pct         = (const float*)d_in[7];   // (4,4096,3)
  const float* cp          = (const float*)d_in[8];   // (1,5,3)
  const float* cps         = (const float*)d_in[9];   // (1,5,3)

  k_nn1 <<<NQGROUP*NSPLIT, 256>>>(pred_points, pcp, pcw, pcr, pct, cp, cps);
  k_main<<<MAIN_BLOCKS, 256>>>(pred_grasps, pred_scores, gwh, cp, cps,
                               (float*)d_out, out_size);
}